// round 1
// baseline (speedup 1.0000x reference)
#include <cuda_runtime.h>

// Problem constants
#define TP 94
#define NN 128
#define HH 32

// h[t][n][c] staging buffer (1.54 MB) — __device__ global, no allocation.
__device__ float g_h[TP * NN * HH];

// ---------------------------------------------------------------------------
// Kernel 1: conv stack.  One block per sequence n (128 blocks, 128 threads).
// Thread index = time position.  Staged through padded smem (stride 17 / 33
// keeps neighbor reads h[(t+k)*stride+ic] bank-conflict free since 17,33 are
// odd/coprime with 32).
// ---------------------------------------------------------------------------
__global__ void __launch_bounds__(128) conv_kernel(
    const float* __restrict__ x,
    const float* __restrict__ w1, const float* __restrict__ b1,
    const float* __restrict__ w2, const float* __restrict__ b2,
    const float* __restrict__ w3, const float* __restrict__ b3)
{
    __shared__ float x_s[400];
    __shared__ float w1_s[192], b1_s[16];
    __shared__ float w2_s[1536], b2_s[32];
    __shared__ float w3_s[3072], b3_s[32];
    __shared__ float h1_s[98 * 17];
    __shared__ float h2_s[96 * 33];

    const int n = blockIdx.x;
    const int tid = threadIdx.x;

    for (int idx = tid; idx < 400;  idx += 128) x_s[idx]  = x[n * 400 + idx];
    for (int idx = tid; idx < 192;  idx += 128) w1_s[idx] = w1[idx];
    for (int idx = tid; idx < 1536; idx += 128) w2_s[idx] = w2[idx];
    for (int idx = tid; idx < 3072; idx += 128) w3_s[idx] = w3[idx];
    if (tid < 16) b1_s[tid] = b1[tid];
    if (tid < 32) { b2_s[tid] = b2[tid]; b3_s[tid] = b3[tid]; }
    __syncthreads();

    const int t = tid;

    // Stage 1: conv1 4->16, T 100->98
    if (t < 98) {
        float xv[12];
        #pragma unroll
        for (int k = 0; k < 3; k++)
            #pragma unroll
            for (int i = 0; i < 4; i++)
                xv[k * 4 + i] = x_s[(t + k) * 4 + i];
        #pragma unroll
        for (int oc = 0; oc < 16; oc++) {
            float acc = b1_s[oc];
            #pragma unroll
            for (int i = 0; i < 4; i++)
                #pragma unroll
                for (int k = 0; k < 3; k++)
                    acc += xv[k * 4 + i] * w1_s[(oc * 4 + i) * 3 + k];
            h1_s[t * 17 + oc] = fmaxf(acc, 0.f);
        }
    }
    __syncthreads();

    // Stage 2: conv2 16->32, T 98->96
    if (t < 96) {
        float acc[32];
        #pragma unroll
        for (int oc = 0; oc < 32; oc++) acc[oc] = b2_s[oc];
        for (int ic = 0; ic < 16; ic++) {
            float h0 = h1_s[(t + 0) * 17 + ic];
            float h1v = h1_s[(t + 1) * 17 + ic];
            float h2v = h1_s[(t + 2) * 17 + ic];
            #pragma unroll
            for (int oc = 0; oc < 32; oc++) {
                const float* w = &w2_s[(oc * 16 + ic) * 3];
                acc[oc] += h0 * w[0] + h1v * w[1] + h2v * w[2];
            }
        }
        #pragma unroll
        for (int oc = 0; oc < 32; oc++)
            h2_s[t * 33 + oc] = fmaxf(acc[oc], 0.f);
    }
    __syncthreads();

    // Stage 3: conv3 32->32, T 96->94, write h[t][n][c]
    if (t < 94) {
        float acc[32];
        #pragma unroll
        for (int oc = 0; oc < 32; oc++) acc[oc] = b3_s[oc];
        for (int ic = 0; ic < 32; ic++) {
            float h0 = h2_s[(t + 0) * 33 + ic];
            float h1v = h2_s[(t + 1) * 33 + ic];
            float h2v = h2_s[(t + 2) * 33 + ic];
            #pragma unroll
            for (int oc = 0; oc < 32; oc++) {
                const float* w = &w3_s[(oc * 32 + ic) * 3];
                acc[oc] += h0 * w[0] + h1v * w[1] + h2v * w[2];
            }
        }
        #pragma unroll
        for (int oc = 0; oc < 32; oc++)
            g_h[(t * NN + n) * HH + oc] = fmaxf(acc[oc], 0.f);
    }
}

// ---------------------------------------------------------------------------
// Kernel 2: everything after the convs.  One block per t (94 blocks, 256 thr).
// ejT stored [d][j] with row stride 132 (16B-aligned rows, 4*d+j bank pattern
// makes float4 loads conflict-free).  Per-thread mapping (i = p>>5, d = lane)
// makes every smem GEMM read either a broadcast or stride-1.
// ---------------------------------------------------------------------------
__global__ void __launch_bounds__(256) swarm_kernel(
    const float* __restrict__ x,
    const float* __restrict__ We, const float* __restrict__ be,
    const float* __restrict__ Wa, const float* __restrict__ ba,
    const float* __restrict__ Wu, const float* __restrict__ bu,
    const float* __restrict__ Wd, const float* __restrict__ bd,
    float* __restrict__ out)
{
    extern __shared__ float s[];
    float* h_s  = s;           // 128*33 = 4224
    float* ejT  = s + 4224;    // 32*132 = 4224  (16B aligned: 4224*4 % 16 == 0)
    float* ci_s = s + 8448;    // 128*32 = 4096
    float* agA  = s + 12544;   // 128*33 = 4224
    float* agB  = s + 16768;   // 128*33 = 4224
    float* upd  = s + 20992;   // 128*33 = 4224
    float* We_s = s + 25216;   // 2048
    float* be_s = s + 27264;   // 32
    float* Wa_s = s + 27296;   // 1024
    float* ba_s = s + 28320;   // 32
    float* Wu_s = s + 28352;   // 2048
    float* bu_s = s + 30400;   // 32
    float* Wd_s = s + 30432;   // 128
    float* bd_s = s + 30560;   // 4
    // total 30564 floats = 122256 B

    const int t = blockIdx.x;
    const int tid = threadIdx.x;

    for (int idx = tid; idx < 4096; idx += 256) {
        int i = idx >> 5, c = idx & 31;
        h_s[i * 33 + c] = g_h[t * 4096 + idx];
    }
    for (int idx = tid; idx < 2048; idx += 256) We_s[idx] = We[idx];
    for (int idx = tid; idx < 2048; idx += 256) Wu_s[idx] = Wu[idx];
    for (int idx = tid; idx < 1024; idx += 256) Wa_s[idx] = Wa[idx];
    if (tid < 32) { be_s[tid] = be[tid]; ba_s[tid] = ba[tid]; bu_s[tid] = bu[tid]; }
    if (tid < 128) Wd_s[tid] = Wd[tid];
    if (tid < 4)  bd_s[tid] = bd[tid];
    __syncthreads();

    // P1: ej (transposed) and ci = ei + be
    for (int k = 0; k < 16; k++) {
        int p = k * 256 + tid;
        int j = p >> 5, d = p & 31;
        float aej = 0.f, aei = be_s[d];
        #pragma unroll
        for (int c = 0; c < 32; c++) {
            float hv = h_s[j * 33 + c];           // broadcast within warp
            aej += hv * We_s[c * 32 + d];         // stride-1 across lanes
            aei += hv * We_s[(32 + c) * 32 + d];
        }
        ejT[d * 132 + j] = aej;
        ci_s[j * 32 + d] = aei;
    }
    __syncthreads();

    // P2: pairwise relu-sum minus diagonal
    for (int k = 0; k < 16; k++) {
        int p = k * 256 + tid;
        int i = p >> 5, d = p & 31;
        float c = ci_s[i * 32 + d];
        float acc = 0.f;
        const float4* row = (const float4*)&ejT[d * 132];
        #pragma unroll 8
        for (int j4 = 0; j4 < 32; j4++) {
            float4 v = row[j4];
            acc += fmaxf(v.x + c, 0.f);
            acc += fmaxf(v.y + c, 0.f);
            acc += fmaxf(v.z + c, 0.f);
            acc += fmaxf(v.w + c, 0.f);
        }
        acc -= fmaxf(ejT[d * 132 + i] + c, 0.f);  // remove diag
        agA[i * 33 + d] = acc;
    }
    __syncthreads();

    // P3: agg = relu(agg @ Wa + ba)
    for (int k = 0; k < 16; k++) {
        int p = k * 256 + tid;
        int i = p >> 5, d = p & 31;
        float acc = ba_s[d];
        #pragma unroll
        for (int c = 0; c < 32; c++)
            acc += agA[i * 33 + c] * Wa_s[c * 32 + d];
        agB[i * 33 + d] = fmaxf(acc, 0.f);
    }
    __syncthreads();

    // P4: upd = relu(h @ Wu[:H] + agg @ Wu[H:] + bu)
    for (int k = 0; k < 16; k++) {
        int p = k * 256 + tid;
        int i = p >> 5, d = p & 31;
        float acc = bu_s[d];
        #pragma unroll
        for (int c = 0; c < 32; c++) {
            acc += h_s[i * 33 + c] * Wu_s[c * 32 + d];
            acc += agB[i * 33 + c] * Wu_s[(32 + c) * 32 + d];
        }
        upd[i * 33 + d] = fmaxf(acc, 0.f);
    }
    __syncthreads();

    // P5: dec = upd @ Wd + bd;  out = x[:, 6+t] + dec
    for (int p = tid; p < 512; p += 256) {
        int i = p >> 2, dd = p & 3;
        float acc = bd_s[dd];
        #pragma unroll
        for (int d = 0; d < 32; d++)
            acc += upd[i * 33 + d] * Wd_s[d * 4 + dd];
        out[(i * TP + t) * 4 + dd] = x[(i * 100 + 6 + t) * 4 + dd] + acc;
    }
}

// ---------------------------------------------------------------------------
extern "C" void kernel_launch(void* const* d_in, const int* in_sizes, int n_in,
                              void* d_out, int out_size)
{
    const float* x  = (const float*)d_in[0];
    const float* w1 = (const float*)d_in[1];
    const float* b1 = (const float*)d_in[2];
    const float* w2 = (const float*)d_in[3];
    const float* b2 = (const float*)d_in[4];
    const float* w3 = (const float*)d_in[5];
    const float* b3 = (const float*)d_in[6];
    const float* We = (const float*)d_in[7];
    const float* be = (const float*)d_in[8];
    const float* Wa = (const float*)d_in[9];
    const float* ba = (const float*)d_in[10];
    const float* Wu = (const float*)d_in[11];
    const float* bu = (const float*)d_in[12];
    const float* Wd = (const float*)d_in[13];
    const float* bd = (const float*)d_in[14];
    float* out = (float*)d_out;

    // 122 KB dynamic smem for swarm_kernel (idempotent, not captured as a node)
    cudaFuncSetAttribute(swarm_kernel,
                         cudaFuncAttributeMaxDynamicSharedMemorySize, 30564 * 4);

    conv_kernel<<<128, 128>>>(x, w1, b1, w2, b2, w3, b3);
    swarm_kernel<<<94, 256, 30564 * 4>>>(x, We, be, Wa, ba, Wu, bu, Wd, bd, out);
}

// round 2
// speedup vs baseline: 1.4060x; 1.4060x over previous
#include <cuda_runtime.h>

#define TP 94
#define NN 128
#define HH 32

__device__ float g_h[TP * NN * HH];

// ---------------------------------------------------------------------------
// Kernel 1: conv stack. One block per n, 256 threads: (half = tid>>7) splits
// output channels so each thread computes 8/16/16 oc per stage.
// ---------------------------------------------------------------------------
__global__ void __launch_bounds__(256) conv_kernel(
    const float* __restrict__ x,
    const float* __restrict__ w1, const float* __restrict__ b1,
    const float* __restrict__ w2, const float* __restrict__ b2,
    const float* __restrict__ w3, const float* __restrict__ b3)
{
    __shared__ float x_s[400];
    __shared__ float w1_s[192], b1_s[16];
    __shared__ float w2_s[1536], b2_s[32];
    __shared__ float w3_s[3072], b3_s[32];
    __shared__ float h1_s[98 * 17];
    __shared__ float h2_s[96 * 33];

    const int n = blockIdx.x;
    const int tid = threadIdx.x;
    const int t = tid & 127;
    const int half = tid >> 7;      // 0 or 1

    for (int idx = tid; idx < 400;  idx += 256) x_s[idx]  = x[n * 400 + idx];
    for (int idx = tid; idx < 192;  idx += 256) w1_s[idx] = w1[idx];
    for (int idx = tid; idx < 1536; idx += 256) w2_s[idx] = w2[idx];
    for (int idx = tid; idx < 3072; idx += 256) w3_s[idx] = w3[idx];
    if (tid < 16) b1_s[tid] = b1[tid];
    if (tid < 32) { b2_s[tid] = b2[tid]; b3_s[tid] = b3[tid]; }
    __syncthreads();

    // Stage 1: conv1 4->16, T 100->98.  Each half does 8 oc.
    if (t < 98) {
        float xv[12];
        #pragma unroll
        for (int k = 0; k < 3; k++)
            #pragma unroll
            for (int i = 0; i < 4; i++)
                xv[k * 4 + i] = x_s[(t + k) * 4 + i];
        const int oc0 = half * 8;
        #pragma unroll
        for (int o = 0; o < 8; o++) {
            int oc = oc0 + o;
            float acc = b1_s[oc];
            #pragma unroll
            for (int i = 0; i < 4; i++)
                #pragma unroll
                for (int k = 0; k < 3; k++)
                    acc += xv[k * 4 + i] * w1_s[(oc * 4 + i) * 3 + k];
            h1_s[t * 17 + oc] = fmaxf(acc, 0.f);
        }
    }
    __syncthreads();

    // Stage 2: conv2 16->32, T 98->96.  Each half does 16 oc.
    if (t < 96) {
        const int oc0 = half * 16;
        float acc[16];
        #pragma unroll
        for (int o = 0; o < 16; o++) acc[o] = b2_s[oc0 + o];
        for (int ic = 0; ic < 16; ic++) {
            float h0 = h1_s[(t + 0) * 17 + ic];
            float h1v = h1_s[(t + 1) * 17 + ic];
            float h2v = h1_s[(t + 2) * 17 + ic];
            #pragma unroll
            for (int o = 0; o < 16; o++) {
                const float* w = &w2_s[((oc0 + o) * 16 + ic) * 3];
                acc[o] += h0 * w[0] + h1v * w[1] + h2v * w[2];
            }
        }
        #pragma unroll
        for (int o = 0; o < 16; o++)
            h2_s[t * 33 + oc0 + o] = fmaxf(acc[o], 0.f);
    }
    __syncthreads();

    // Stage 3: conv3 32->32, T 96->94.  Each half does 16 oc.
    if (t < 94) {
        const int oc0 = half * 16;
        float acc[16];
        #pragma unroll
        for (int o = 0; o < 16; o++) acc[o] = b3_s[oc0 + o];
        for (int ic = 0; ic < 32; ic++) {
            float h0 = h2_s[(t + 0) * 33 + ic];
            float h1v = h2_s[(t + 1) * 33 + ic];
            float h2v = h2_s[(t + 2) * 33 + ic];
            #pragma unroll
            for (int o = 0; o < 16; o++) {
                const float* w = &w3_s[((oc0 + o) * 32 + ic) * 3];
                acc[o] += h0 * w[0] + h1v * w[1] + h2v * w[2];
            }
        }
        #pragma unroll
        for (int o = 0; o < 16; o++)
            g_h[(t * NN + n) * HH + oc0 + o] = fmaxf(acc[o], 0.f);
    }
}

// ---------------------------------------------------------------------------
// Kernel 2: one block per t, 512 threads (16 warps = 4/SMSP).
// Thread mapping everywhere: d = tid&31, g = tid>>5 (16 groups);
// each thread handles rows i/j in {g, g+16, ..., g+112} (8 rows), so one
// shared-operand load is amortized over 8 register accumulators.
// ---------------------------------------------------------------------------
__global__ void __launch_bounds__(512) swarm_kernel(
    const float* __restrict__ x,
    const float* __restrict__ We, const float* __restrict__ be,
    const float* __restrict__ Wa, const float* __restrict__ ba,
    const float* __restrict__ Wu, const float* __restrict__ bu,
    const float* __restrict__ Wd, const float* __restrict__ bd,
    float* __restrict__ out)
{
    extern __shared__ float s[];
    float* h_s  = s;           // 128*33 = 4224
    float* ejT  = s + 4224;    // 32*132 = 4224
    float* ci_s = s + 8448;    // 128*32 = 4096
    float* agA  = s + 12544;   // 128*33 = 4224
    float* agB  = s + 16768;   // 128*33 = 4224
    float* upd  = s + 20992;   // 128*33 = 4224
    float* We_s = s + 25216;   // 2048
    float* be_s = s + 27264;   // 32
    float* Wa_s = s + 27296;   // 1024
    float* ba_s = s + 28320;   // 32
    float* Wu_s = s + 28352;   // 2048
    float* bu_s = s + 30400;   // 32
    float* Wd_s = s + 30432;   // 128
    float* bd_s = s + 30560;   // 4
    // total 30564 floats = 122256 B

    const int t = blockIdx.x;
    const int tid = threadIdx.x;
    const int d = tid & 31;
    const int g = tid >> 5;      // 0..15

    for (int idx = tid; idx < 4096; idx += 512) {
        int i = idx >> 5, c = idx & 31;
        h_s[i * 33 + c] = g_h[t * 4096 + idx];
    }
    for (int idx = tid; idx < 2048; idx += 512) We_s[idx] = We[idx];
    for (int idx = tid; idx < 2048; idx += 512) Wu_s[idx] = Wu[idx];
    for (int idx = tid; idx < 1024; idx += 512) Wa_s[idx] = Wa[idx];
    if (tid < 32) { be_s[tid] = be[tid]; ba_s[tid] = ba[tid]; bu_s[tid] = bu[tid]; }
    else if (tid >= 64 && tid < 192) Wd_s[tid - 64] = Wd[tid - 64];
    else if (tid >= 192 && tid < 196) bd_s[tid - 192] = bd[tid - 192];
    __syncthreads();

    // P1: ejT[d][j] and ci[j][d] = ei + be.  8 j per thread; We loads hoisted.
    {
        float aej[8], aei[8];
        float bev = be_s[d];
        #pragma unroll
        for (int ii = 0; ii < 8; ii++) { aej[ii] = 0.f; aei[ii] = bev; }
        #pragma unroll
        for (int c = 0; c < 32; c++) {
            float wj = We_s[c * 32 + d];
            float wi = We_s[(32 + c) * 32 + d];
            #pragma unroll
            for (int ii = 0; ii < 8; ii++) {
                float hv = h_s[(g + 16 * ii) * 33 + c];   // warp broadcast
                aej[ii] += hv * wj;
                aei[ii] += hv * wi;
            }
        }
        #pragma unroll
        for (int ii = 0; ii < 8; ii++) {
            int j = g + 16 * ii;
            ejT[d * 132 + j] = aej[ii];
            ci_s[j * 32 + d] = aei[ii];
        }
    }
    __syncthreads();

    // P2: agg0[i][d] = sum_j relu(ejT[d][j] + ci[i][d]) - diag.
    // One float4 load of ejT feeds 8 i-accumulators.
    {
        float acc[8], cc[8];
        #pragma unroll
        for (int ii = 0; ii < 8; ii++) {
            cc[ii] = ci_s[(g + 16 * ii) * 32 + d];
            acc[ii] = 0.f;
        }
        const float4* row = (const float4*)&ejT[d * 132];
        #pragma unroll 4
        for (int j4 = 0; j4 < 32; j4++) {
            float4 v = row[j4];
            #pragma unroll
            for (int ii = 0; ii < 8; ii++) {
                acc[ii] += fmaxf(v.x + cc[ii], 0.f);
                acc[ii] += fmaxf(v.y + cc[ii], 0.f);
                acc[ii] += fmaxf(v.z + cc[ii], 0.f);
                acc[ii] += fmaxf(v.w + cc[ii], 0.f);
            }
        }
        #pragma unroll
        for (int ii = 0; ii < 8; ii++) {
            int i = g + 16 * ii;
            acc[ii] -= fmaxf(ejT[d * 132 + i] + cc[ii], 0.f);
            agA[i * 33 + d] = acc[ii];
        }
    }
    __syncthreads();

    // P3: agg = relu(agg0 @ Wa + ba)
    {
        float acc[8];
        float bav = ba_s[d];
        #pragma unroll
        for (int ii = 0; ii < 8; ii++) acc[ii] = bav;
        #pragma unroll
        for (int c = 0; c < 32; c++) {
            float w = Wa_s[c * 32 + d];
            #pragma unroll
            for (int ii = 0; ii < 8; ii++)
                acc[ii] += agA[(g + 16 * ii) * 33 + c] * w;
        }
        #pragma unroll
        for (int ii = 0; ii < 8; ii++)
            agB[(g + 16 * ii) * 33 + d] = fmaxf(acc[ii], 0.f);
    }
    __syncthreads();

    // P4: upd = relu(h @ Wu[:H] + agg @ Wu[H:] + bu)
    {
        float acc[8];
        float buv = bu_s[d];
        #pragma unroll
        for (int ii = 0; ii < 8; ii++) acc[ii] = buv;
        #pragma unroll
        for (int c = 0; c < 32; c++) {
            float wh = Wu_s[c * 32 + d];
            float wa = Wu_s[(32 + c) * 32 + d];
            #pragma unroll
            for (int ii = 0; ii < 8; ii++) {
                int r = (g + 16 * ii) * 33 + c;
                acc[ii] += h_s[r] * wh;
                acc[ii] += agB[r] * wa;
            }
        }
        #pragma unroll
        for (int ii = 0; ii < 8; ii++)
            upd[(g + 16 * ii) * 33 + d] = fmaxf(acc[ii], 0.f);
    }
    __syncthreads();

    // P5: dec = upd @ Wd + bd;  out = x[:, 6+t] + dec.  512 outputs, 1/thread.
    {
        int i = tid >> 2, dd = tid & 3;
        float acc = bd_s[dd];
        #pragma unroll
        for (int dc = 0; dc < 32; dc++)
            acc += upd[i * 33 + dc] * Wd_s[dc * 4 + dd];
        out[(i * TP + t) * 4 + dd] = x[(i * 100 + 6 + t) * 4 + dd] + acc;
    }
}

// ---------------------------------------------------------------------------
extern "C" void kernel_launch(void* const* d_in, const int* in_sizes, int n_in,
                              void* d_out, int out_size)
{
    const float* x  = (const float*)d_in[0];
    const float* w1 = (const float*)d_in[1];
    const float* b1 = (const float*)d_in[2];
    const float* w2 = (const float*)d_in[3];
    const float* b2 = (const float*)d_in[4];
    const float* w3 = (const float*)d_in[5];
    const float* b3 = (const float*)d_in[6];
    const float* We = (const float*)d_in[7];
    const float* be = (const float*)d_in[8];
    const float* Wa = (const float*)d_in[9];
    const float* ba = (const float*)d_in[10];
    const float* Wu = (const float*)d_in[11];
    const float* bu = (const float*)d_in[12];
    const float* Wd = (const float*)d_in[13];
    const float* bd = (const float*)d_in[14];
    float* out = (float*)d_out;

    cudaFuncSetAttribute(swarm_kernel,
                         cudaFuncAttributeMaxDynamicSharedMemorySize, 30564 * 4);

    conv_kernel<<<128, 256>>>(x, w1, b1, w2, b2, w3, b3);
    swarm_kernel<<<94, 512, 30564 * 4>>>(x, We, be, Wa, ba, Wu, bu, Wd, bd, out);
}